// round 2
// baseline (speedup 1.0000x reference)
#include <cuda_runtime.h>
#include <cuda_bf16.h>

#define B_   512
#define N_   50
#define D_   128
#define H_   200
#define E_   50000
#define KPAD 208            // H_ padded to 13*16 for mma
#define KU   (KPAD/2)       // 104 uints per row
#define NPART 782           // ceil(E_/64)

// ---------------- static device scratch ----------------
__device__ __nv_bfloat16 g_wb[E_ * KPAD];   // mlp_w bf16, K-padded
__device__ __nv_bfloat16 g_vb[B_ * KPAD];   // poses bf16, K-padded
__device__ float g_part[B_ * NPART];        // per-(row, e-block) partial sum(exp)
__device__ float g_invZs[B_];               // 0.5 / Z_s
__device__ float g_pbase[B_];               // 0.5 * exp(-m_p) / Z_p
__device__ float g_fix_p[B_ * N_];          // per distinct id: p-term, then final value
__device__ int   g_fix_id[B_ * N_];
__device__ int   g_fix_cnt[B_];

// ---------------- K0: mlp_w fp32 -> bf16 padded ----------------
__global__ void k_convert(const float* __restrict__ w) {
    int i = blockIdx.x * 256 + threadIdx.x;
    if (i >= E_ * KPAD) return;
    int e = i / KPAD, c = i - e * KPAD;
    g_wb[i] = __float2bfloat16((c < H_) ? w[e * H_ + c] : 0.f);
}

// ---------------- K1: gather + projection + routing (one block per batch row) ----------------
#define SW_STR 129
__global__ void __launch_bounds__(256) k_routing(
    const int* __restrict__ idx, const int* __restrict__ times,
    const float* __restrict__ emb, const float* __restrict__ Ws_w,
    const float* __restrict__ Ws_b)
{
    extern __shared__ float sm[];
    float* sW  = sm;                    // [200][129]
    float* sE  = sW + 200 * SW_STR;     // [50][128]
    float* sU  = sE + 50 * 128;         // [50][200]
    float* sB  = sU + 50 * 200;         // [50]
    float* sC  = sB + 50;               // [50]
    float* sV  = sC + 50;               // [200]
    float* sTmp= sV + 200;              // [50]
    float* sRed= sTmp + 50;             // [9]
    int*   sIdx= (int*)(sRed + 9);      // [50]

    const int tid = threadIdx.x;
    const int lane = tid & 31, wid = tid >> 5;
    const int row = blockIdx.x;

    if (tid < 50) {
        sIdx[tid] = idx[row * N_ + tid];
        sB[tid] = 2.0f / (1.0f + (float)times[row * N_ + tid]);
    }
    for (int i = tid; i < 200 * 128; i += 256) {
        int h = i >> 7, d = i & 127;
        sW[h * SW_STR + d] = Ws_w[i];
    }
    for (int i = tid; i < 50 * 128; i += 256) {
        int n = i >> 7, d = i & 127;
        sE[i] = emb[idx[row * N_ + n] * D_ + d];
    }
    __syncthreads();

    // x = embeds @ Ws^T + b, register-blocked 5x8, 250 active threads
    if (tid < 250) {
        int tn = tid / 25, th = tid - tn * 25;
        float acc[5][8];
#pragma unroll
        for (int i = 0; i < 5; i++)
#pragma unroll
            for (int j = 0; j < 8; j++) acc[i][j] = 0.f;
#pragma unroll 4
        for (int d = 0; d < 128; d++) {
            float a[5], bv[8];
#pragma unroll
            for (int i = 0; i < 5; i++) a[i] = sE[(tn * 5 + i) * 128 + d];
#pragma unroll
            for (int j = 0; j < 8; j++) bv[j] = sW[(th + 25 * j) * SW_STR + d];
#pragma unroll
            for (int i = 0; i < 5; i++)
#pragma unroll
                for (int j = 0; j < 8; j++) acc[i][j] = fmaf(a[i], bv[j], acc[i][j]);
        }
#pragma unroll
        for (int j = 0; j < 8; j++) {
            int h = th + 25 * j;
            float bias = Ws_b[h];
#pragma unroll
            for (int i = 0; i < 5; i++)
                sU[(tn * 5 + i) * H_ + h] = acc[i][j] + bias;
        }
    }
    __syncthreads();

    // L2 normalize rows of sU over H (one warp per n-row)
    for (int n = wid; n < 50; n += 8) {
        float ss = 0.f;
        for (int h = lane; h < H_; h += 32) { float v = sU[n * H_ + h]; ss += v * v; }
#pragma unroll
        for (int o = 16; o > 0; o >>= 1) ss += __shfl_xor_sync(0xffffffffu, ss, o);
        float inv = 1.0f / fmaxf(sqrtf(ss), 1e-12f);
        for (int h = lane; h < H_; h += 32) sU[n * H_ + h] *= inv;
    }
    __syncthreads();

    // dynamic routing, 3 iterations
    for (int r = 0; r < 3; r++) {
        if (wid == 0) {
            float v0 = (lane < 50) ? sB[lane] : -1e30f;
            float v1 = (lane + 32 < 50) ? sB[lane + 32] : -1e30f;
            float m = fmaxf(v0, v1);
#pragma unroll
            for (int o = 16; o > 0; o >>= 1) m = fmaxf(m, __shfl_xor_sync(0xffffffffu, m, o));
            float e0 = (lane < 50) ? expf(v0 - m) : 0.f;
            float e1 = (lane + 32 < 50) ? expf(v1 - m) : 0.f;
            float s = e0 + e1;
#pragma unroll
            for (int o = 16; o > 0; o >>= 1) s += __shfl_xor_sync(0xffffffffu, s, o);
            float sc = 50.0f / s;
            if (lane < 50) sC[lane] = e0 * sc;
            if (lane + 32 < 50) sC[lane + 32] = e1 * sc;
        }
        __syncthreads();
        float mysq = 0.f;
        if (tid < H_) {
            float sv = 0.f;
#pragma unroll 5
            for (int n = 0; n < 50; n++) sv += sC[n] * sU[n * H_ + tid];
            sV[tid] = sv;
            mysq = sv * sv;
        }
#pragma unroll
        for (int o = 16; o > 0; o >>= 1) mysq += __shfl_xor_sync(0xffffffffu, mysq, o);
        if (lane == 0) sRed[wid] = mysq;
        __syncthreads();
        if (tid == 0) {
            float sq = 0.f;
#pragma unroll
            for (int i = 0; i < 8; i++) sq += sRed[i];
            sRed[8] = sq / ((1.0f + sq) * sqrtf(sq + 1e-9f));
        }
        __syncthreads();
        if (tid < H_) sV[tid] *= sRed[8];
        __syncthreads();
        if (r < 2) {
            for (int n = wid; n < 50; n += 8) {
                float dot = 0.f;
                for (int h = lane; h < H_; h += 32) dot += sU[n * H_ + h] * sV[h];
#pragma unroll
                for (int o = 16; o > 0; o >>= 1) dot += __shfl_xor_sync(0xffffffffu, dot, o);
                if (lane == 0) sB[n] += dot;
            }
            __syncthreads();
        }
    }

    // outputs: poses (bf16 padded) + sparse-p preparation
    if (tid < H_)
        g_vb[row * KPAD + tid] = __float2bfloat16(sV[tid]);
    else if (tid < KPAD)
        g_vb[row * KPAD + tid] = __float2bfloat16(0.f);

    if (tid < 50) {
        int my = sIdx[tid];
        bool first = true;
        float cs = 0.f;
        for (int m = 0; m < 50; m++) {
            if (sIdx[m] == my) {
                cs += sC[m];
                if (m < tid) first = false;
            }
        }
        sTmp[tid] = first ? cs : -1.0f;   // valid sums are > 0
    }
    __syncthreads();
    if (tid == 0) {
        float mp = -1e30f; int K = 0;
        for (int n = 0; n < 50; n++)
            if (sTmp[n] >= 0.f) { K++; mp = fmaxf(mp, sTmp[n]); }
        float Zp = (float)(E_ - K) * expf(-mp);
        for (int n = 0; n < 50; n++)
            if (sTmp[n] >= 0.f) Zp += expf(sTmp[n] - mp);
        int slot = 0;
        for (int n = 0; n < 50; n++)
            if (sTmp[n] >= 0.f) {
                g_fix_id[row * N_ + slot] = sIdx[n];
                g_fix_p[row * N_ + slot] = 0.5f * expf(sTmp[n] - mp) / Zp;
                slot++;
            }
        g_fix_cnt[row] = K;
        g_pbase[row] = 0.5f * expf(-mp) / Zp;
    }
}

// ---------------- K2: bf16 mma GEMM, scores -> d_out + deterministic exp partials ----------------
#define GBM 128
#define GBN 64
#define SAS 216   // padded bf16 stride

__device__ __forceinline__ void mma16816(float* c, const unsigned* a, const unsigned* b) {
    asm volatile("mma.sync.aligned.m16n8k16.row.col.f32.bf16.bf16.f32 "
        "{%0,%1,%2,%3}, {%4,%5,%6,%7}, {%8,%9}, {%0,%1,%2,%3};"
        : "+f"(c[0]), "+f"(c[1]), "+f"(c[2]), "+f"(c[3])
        : "r"(a[0]), "r"(a[1]), "r"(a[2]), "r"(a[3]), "r"(b[0]), "r"(b[1]));
}

__global__ void __launch_bounds__(256) k_gemm(const float* __restrict__ mlp_b,
                                              float* __restrict__ out)
{
    extern __shared__ __align__(16) char gsm[];
    __nv_bfloat16* sA = (__nv_bfloat16*)gsm;      // [128][SAS]
    __nv_bfloat16* sBm = sA + GBM * SAS;          // [64][SAS]
    __shared__ float s_part[GBM][8];

    const int tid = threadIdx.x;
    const int eBase = blockIdx.x * GBN;
    const int rBase = blockIdx.y * GBM;

    const unsigned* gv = (const unsigned*)g_vb;
    for (int i = tid; i < GBM * KU; i += 256) {
        int r = i / KU, c = i - r * KU;
        ((unsigned*)(sA + r * SAS))[c] = gv[(rBase + r) * KU + c];
    }
    const unsigned* gw = (const unsigned*)g_wb;
    for (int i = tid; i < GBN * KU; i += 256) {
        int r = i / KU, c = i - r * KU;
        int e = eBase + r;
        ((unsigned*)(sBm + r * SAS))[c] = (e < E_) ? gw[e * KU + c] : 0u;
    }
    __syncthreads();

    const int lane = tid & 31, warp = tid >> 5;
    const int gid = lane >> 2, tig = lane & 3;
    const int wm = warp & 3, wn = warp >> 2;   // 4(m) x 2(n) warps, each 32x32

    float acc[2][4][4];
#pragma unroll
    for (int mi = 0; mi < 2; mi++)
#pragma unroll
        for (int ni = 0; ni < 4; ni++)
#pragma unroll
            for (int q = 0; q < 4; q++) acc[mi][ni][q] = 0.f;

#pragma unroll
    for (int ks = 0; ks < 13; ks++) {
        const int k0 = ks * 16;
        unsigned a[2][4], bf[4][2];
#pragma unroll
        for (int mi = 0; mi < 2; mi++) {
            const __nv_bfloat16* base = sA + (wm * 32 + mi * 16 + gid) * SAS + k0 + 2 * tig;
            a[mi][0] = *(const unsigned*)base;
            a[mi][1] = *(const unsigned*)(base + 8 * SAS);
            a[mi][2] = *(const unsigned*)(base + 8);
            a[mi][3] = *(const unsigned*)(base + 8 * SAS + 8);
        }
#pragma unroll
        for (int ni = 0; ni < 4; ni++) {
            const __nv_bfloat16* base = sBm + (wn * 32 + ni * 8 + gid) * SAS + k0 + 2 * tig;
            bf[ni][0] = *(const unsigned*)base;
            bf[ni][1] = *(const unsigned*)(base + 8);
        }
#pragma unroll
        for (int mi = 0; mi < 2; mi++)
#pragma unroll
            for (int ni = 0; ni < 4; ni++)
                mma16816(acc[mi][ni], a[mi], bf[ni]);
    }

    // epilogue: bias, store scores, fixed-order exp partials
    float rs[2][2] = {{0.f, 0.f}, {0.f, 0.f}};
#pragma unroll
    for (int mi = 0; mi < 2; mi++) {
        int r0 = rBase + wm * 32 + mi * 16 + gid;
#pragma unroll
        for (int ni = 0; ni < 4; ni++) {
            int e0 = eBase + wn * 32 + ni * 8 + 2 * tig;
            if (e0 < E_) {
                float b0 = mlp_b[e0], b1 = mlp_b[e0 + 1];
                float s00 = acc[mi][ni][0] + b0;
                float s01 = acc[mi][ni][1] + b1;
                float s10 = acc[mi][ni][2] + b0;
                float s11 = acc[mi][ni][3] + b1;
                out[(size_t)r0 * E_ + e0]            = s00;
                out[(size_t)r0 * E_ + e0 + 1]        = s01;
                out[(size_t)(r0 + 8) * E_ + e0]      = s10;
                out[(size_t)(r0 + 8) * E_ + e0 + 1]  = s11;
                rs[mi][0] += __expf(s00) + __expf(s01);
                rs[mi][1] += __expf(s10) + __expf(s11);
            }
        }
    }
    const int slot = wn * 4 + tig;
#pragma unroll
    for (int mi = 0; mi < 2; mi++) {
        s_part[wm * 32 + mi * 16 + gid][slot]     = rs[mi][0];
        s_part[wm * 32 + mi * 16 + gid + 8][slot] = rs[mi][1];
    }
    __syncthreads();
    if (tid < GBM) {
        float s = 0.f;
#pragma unroll
        for (int j = 0; j < 8; j++) s += s_part[tid][j];
        g_part[(size_t)(rBase + tid) * NPART + blockIdx.x] = s;
    }
}

// ---------------- K3: reduce partials -> 0.5/Z_s per row (deterministic) ----------------
__global__ void __launch_bounds__(256) k_reduce() {
    __shared__ float red[256];
    const int row = blockIdx.x, tid = threadIdx.x;
    float s = 0.f;
    for (int p = tid; p < NPART; p += 256) s += g_part[(size_t)row * NPART + p];
    red[tid] = s;
    __syncthreads();
    for (int o = 128; o > 0; o >>= 1) {
        if (tid < o) red[tid] += red[tid + o];
        __syncthreads();
    }
    if (tid == 0) g_invZs[row] = 0.5f / red[0];
}

// ---------------- K4: pre-compute fixup values (reads raw scores) ----------------
__global__ void k_fix_pre() {
    const int row = blockIdx.x, t = threadIdx.x;
    if (t < g_fix_cnt[row]) {
        int id = g_fix_id[row * N_ + t];
        float s = ((const float*)0, 0.f);  // placeholder avoided
    }
}

// real version (separate to keep out pointer):
__global__ void k_fix_pre2(const float* __restrict__ out) {
    const int row = blockIdx.x, t = threadIdx.x;
    if (t < g_fix_cnt[row]) {
        int id = g_fix_id[row * N_ + t];
        float s = out[(size_t)row * E_ + id];
        float val = __logf(g_fix_p[row * N_ + t] + g_invZs[row] * __expf(s));
        g_fix_p[row * N_ + t] = val;
    }
}

// ---------------- K5: finalize whole output (float4) ----------------
__global__ void __launch_bounds__(256) k_finalize(float* __restrict__ out) {
    const int row = blockIdx.y;
    const int q = blockIdx.x * 256 + threadIdx.x;     // float4 index within row
    if (q >= E_ / 4) return;
    float4* p = (float4*)(out + (size_t)row * E_) + q;
    float4 v = *p;
    const float pb = g_pbase[row], iz = g_invZs[row];
    v.x = __logf(pb + iz * __expf(v.x));
    v.y = __logf(pb + iz * __expf(v.y));
    v.z = __logf(pb + iz * __expf(v.z));
    v.w = __logf(pb + iz * __expf(v.w));
    *p = v;
}

// ---------------- K6: write fixed values for history ids ----------------
__global__ void k_fix_post(float* __restrict__ out) {
    const int row = blockIdx.x, t = threadIdx.x;
    if (t < g_fix_cnt[row]) {
        int id = g_fix_id[row * N_ + t];
        out[(size_t)row * E_ + id] = g_fix_p[row * N_ + t];
    }
}

// ---------------- launch ----------------
extern "C" void kernel_launch(void* const* d_in, const int* in_sizes, int n_in,
                              void* d_out, int out_size) {
    const int*   idx   = (const int*)d_in[0];
    const int*   times = (const int*)d_in[1];
    const float* emb   = (const float*)d_in[2];
    const float* Ws_w  = (const float*)d_in[3];
    const float* Ws_b  = (const float*)d_in[4];
    const float* mlp_w = (const float*)d_in[5];
    const float* mlp_b = (const float*)d_in[6];
    float* out = (float*)d_out;

    static bool attr_done = false;
    const int rout_smem = (200 * SW_STR + 50 * 128 + 50 * 200 + 50 + 50 + 200 + 50 + 9 + 50) * 4;
    const int gemm_smem = (GBM + GBN) * SAS * 2;
    if (!attr_done) {
        cudaFuncSetAttribute(k_routing, cudaFuncAttributeMaxDynamicSharedMemorySize, rout_smem);
        cudaFuncSetAttribute(k_gemm,    cudaFuncAttributeMaxDynamicSharedMemorySize, gemm_smem);
        attr_done = true;
    }

    k_convert<<<(E_ * KPAD + 255) / 256, 256>>>(mlp_w);
    k_routing<<<B_, 256, rout_smem>>>(idx, times, emb, Ws_w, Ws_b);
    dim3 gg(NPART, B_ / GBM);
    k_gemm<<<gg, 256, gemm_smem>>>(mlp_b, out);
    k_reduce<<<B_, 256>>>();
    k_fix_pre2<<<B_, 64>>>(out);
    dim3 gf((E_ / 4 + 255) / 256, B_);
    k_finalize<<<gf, 256>>>(out);
    k_fix_post<<<B_, 64>>>(out);
}